// round 1
// baseline (speedup 1.0000x reference)
#include <cuda_runtime.h>
#include <cstdint>

#define NP 100000
#define NA 50000
#define H  128

// ---------------- device scratch (no allocations allowed) ----------------
__device__ float g_acc_c[(size_t)NP * H];   // cites  accumulator (paper dst)
__device__ float g_acc_w[(size_t)NP * H];   // writes accumulator (paper dst)
__device__ float g_acc_r[(size_t)NA * H];   // rev    accumulator (author dst)
__device__ float g_Oc[(size_t)NP * H];
__device__ float g_Ow[(size_t)NP * H];
__device__ float g_Or[(size_t)NA * H];
__device__ float g_xp[(size_t)NP * H];      // layer-0 paper output
__device__ float g_xa[(size_t)NA * H];      // layer-0 author output
__device__ float g_cnt_c[NP];
__device__ float g_cnt_w[NP];
__device__ float g_cnt_r[NA];

// ---------------- kernels ----------------

__global__ void count_kernel(const int* __restrict__ dst, float* __restrict__ cnt, int nE) {
    int e = blockIdx.x * blockDim.x + threadIdx.x;
    if (e < nE) atomicAdd(&cnt[dst[e]], 1.0f);
}

// in-place: cnt -> 1/max(cnt,1)
__global__ void inv_kernel(float* __restrict__ c, int n) {
    int i = blockIdx.x * blockDim.x + threadIdx.x;
    if (i < n) c[i] = 1.0f / fmaxf(c[i], 1.0f);
}

// warp per edge: gather src row (float4/lane), vector-RED into acc[dst]
__global__ void scatter_kernel(const float* __restrict__ x, const int* __restrict__ src,
                               const int* __restrict__ dst, float* __restrict__ acc, int nE) {
    int gw   = (blockIdx.x * blockDim.x + threadIdx.x) >> 5;
    int lane = threadIdx.x & 31;
    if (gw >= nE) return;
    int s = __ldg(&src[gw]);
    int d = __ldg(&dst[gw]);
    float4 v = *(const float4*)(x + (size_t)s * H + lane * 4);
    float* p = acc + (size_t)d * H + lane * 4;
    unsigned long long gp = (unsigned long long)__cvta_generic_to_global(p);
    asm volatile("red.global.add.v4.f32 [%0], {%1, %2, %3, %4};"
                 :: "l"(gp), "f"(v.x), "f"(v.y), "f"(v.z), "f"(v.w) : "memory");
}

// O[n x 128] = [acc*invcnt | xdst] (n x 256) @ [[Wl],[Wr]] (256 x 128) + bias
// tile 128x128, K-chunks of 32, 256 threads, 8x8 micro-tile
__global__ void __launch_bounds__(256, 2) sage_gemm(
    const float* __restrict__ acc, const float* __restrict__ invc,
    const float* __restrict__ xdst,
    const float* __restrict__ Wl, const float* __restrict__ Wr,
    const float* __restrict__ bias, float* __restrict__ O, int n)
{
    __shared__ float As[32][132];   // [k][m], padded
    __shared__ float Bs[32][128];   // [k][n]
    const int row0 = blockIdx.x * 128;
    const int tid  = threadIdx.x;
    const int tx = tid & 15, ty = tid >> 4;
    const int r0 = ty * 8, c0 = tx * 8;

    float accr[8][8];
    float bv[8];
#pragma unroll
    for (int j = 0; j < 8; j++) bv[j] = __ldg(&bias[c0 + j]);
#pragma unroll
    for (int i = 0; i < 8; i++)
#pragma unroll
        for (int j = 0; j < 8; j++) accr[i][j] = bv[j];

    for (int kt = 0; kt < 2 * H; kt += 32) {
        // ---- load A tile (transpose to [k][m]) ----
#pragma unroll
        for (int l = 0; l < 4; l++) {
            int idx = tid + l * 256;        // 0..1023
            int m   = idx >> 3;             // row within tile
            int kv  = idx & 7;              // float4 index within k-chunk
            int grow = row0 + m;
            int kg   = kt + kv * 4;
            float4 v = make_float4(0.f, 0.f, 0.f, 0.f);
            if (grow < n) {
                if (kg < H) {
                    v = *(const float4*)(acc + (size_t)grow * H + kg);
                    float ic = __ldg(&invc[grow]);
                    v.x *= ic; v.y *= ic; v.z *= ic; v.w *= ic;
                } else {
                    v = *(const float4*)(xdst + (size_t)grow * H + (kg - H));
                }
            }
            int kl = kv * 4;
            As[kl + 0][m] = v.x; As[kl + 1][m] = v.y;
            As[kl + 2][m] = v.z; As[kl + 3][m] = v.w;
        }
        // ---- load B tile ----
#pragma unroll
        for (int l = 0; l < 4; l++) {
            int idx = tid + l * 256;
            int kl  = idx >> 5;             // 0..31
            int cv  = idx & 31;             // float4 col index
            int kg  = kt + kl;
            const float* Wp = (kg < H) ? (Wl + (size_t)kg * H) : (Wr + (size_t)(kg - H) * H);
            *(float4*)&Bs[kl][cv * 4] = *(const float4*)(Wp + cv * 4);
        }
        __syncthreads();
#pragma unroll
        for (int kk = 0; kk < 32; kk++) {
            float a[8], b[8];
            *(float4*)&a[0] = *(const float4*)&As[kk][r0];
            *(float4*)&a[4] = *(const float4*)&As[kk][r0 + 4];
            *(float4*)&b[0] = *(const float4*)&Bs[kk][c0];
            *(float4*)&b[4] = *(const float4*)&Bs[kk][c0 + 4];
#pragma unroll
            for (int i = 0; i < 8; i++)
#pragma unroll
                for (int j = 0; j < 8; j++) accr[i][j] += a[i] * b[j];
        }
        __syncthreads();
    }
#pragma unroll
    for (int i = 0; i < 8; i++) {
        int grow = row0 + r0 + i;
        if (grow < n) {
            *(float4*)(O + (size_t)grow * H + c0)     =
                make_float4(accr[i][0], accr[i][1], accr[i][2], accr[i][3]);
            *(float4*)(O + (size_t)grow * H + c0 + 4) =
                make_float4(accr[i][4], accr[i][5], accr[i][6], accr[i][7]);
        }
    }
}

// warp per node: relu(0.5*(normalize(Oc) + normalize(Ow)))
__global__ void finalize_paper(const float* __restrict__ Oc, const float* __restrict__ Ow,
                               float* __restrict__ out) {
    int gw   = (blockIdx.x * blockDim.x + threadIdx.x) >> 5;
    int lane = threadIdx.x & 31;
    if (gw >= NP) return;
    float4 c = *(const float4*)(Oc + (size_t)gw * H + lane * 4);
    float4 w = *(const float4*)(Ow + (size_t)gw * H + lane * 4);
    float sc = c.x*c.x + c.y*c.y + c.z*c.z + c.w*c.w;
    float sw = w.x*w.x + w.y*w.y + w.z*w.z + w.w*w.w;
#pragma unroll
    for (int o = 16; o > 0; o >>= 1) {
        sc += __shfl_xor_sync(0xffffffffu, sc, o);
        sw += __shfl_xor_sync(0xffffffffu, sw, o);
    }
    float ic = 0.5f / fmaxf(sqrtf(sc), 1e-12f);
    float iw = 0.5f / fmaxf(sqrtf(sw), 1e-12f);
    float4 r;
    r.x = fmaxf(c.x * ic + w.x * iw, 0.f);
    r.y = fmaxf(c.y * ic + w.y * iw, 0.f);
    r.z = fmaxf(c.z * ic + w.z * iw, 0.f);
    r.w = fmaxf(c.w * ic + w.w * iw, 0.f);
    *(float4*)(out + (size_t)gw * H + lane * 4) = r;
}

// warp per node: relu(normalize(Or))
__global__ void finalize_author(const float* __restrict__ Or, float* __restrict__ out) {
    int gw   = (blockIdx.x * blockDim.x + threadIdx.x) >> 5;
    int lane = threadIdx.x & 31;
    if (gw >= NA) return;
    float4 c = *(const float4*)(Or + (size_t)gw * H + lane * 4);
    float sc = c.x*c.x + c.y*c.y + c.z*c.z + c.w*c.w;
#pragma unroll
    for (int o = 16; o > 0; o >>= 1) sc += __shfl_xor_sync(0xffffffffu, sc, o);
    float ic = 1.0f / fmaxf(sqrtf(sc), 1e-12f);
    float4 r;
    r.x = fmaxf(c.x * ic, 0.f);
    r.y = fmaxf(c.y * ic, 0.f);
    r.z = fmaxf(c.z * ic, 0.f);
    r.w = fmaxf(c.w * ic, 0.f);
    *(float4*)(out + (size_t)gw * H + lane * 4) = r;
}

// ---------------- host launcher ----------------
extern "C" void kernel_launch(void* const* d_in, const int* in_sizes, int n_in,
                              void* d_out, int out_size) {
    const float* x_paper  = (const float*)d_in[0];
    const float* x_author = (const float*)d_in[1];
    const int* cs = (const int*)d_in[2];
    const int* cd = (const int*)d_in[3];
    const int* ws = (const int*)d_in[4];
    const int* wd = (const int*)d_in[5];
    const int* rs = (const int*)d_in[6];
    const int* rd = (const int*)d_in[7];
    const int EC = in_sizes[2];
    const int EW = in_sizes[4];
    const float* W[18];
    for (int i = 0; i < 18; i++) W[i] = (const float*)d_in[8 + i];

    float *acc_c, *acc_w, *acc_r, *Oc, *Ow, *Or, *xp, *xa, *cnt_c, *cnt_w, *cnt_r;
    cudaGetSymbolAddress((void**)&acc_c, g_acc_c);
    cudaGetSymbolAddress((void**)&acc_w, g_acc_w);
    cudaGetSymbolAddress((void**)&acc_r, g_acc_r);
    cudaGetSymbolAddress((void**)&Oc, g_Oc);
    cudaGetSymbolAddress((void**)&Ow, g_Ow);
    cudaGetSymbolAddress((void**)&Or, g_Or);
    cudaGetSymbolAddress((void**)&xp, g_xp);
    cudaGetSymbolAddress((void**)&xa, g_xa);
    cudaGetSymbolAddress((void**)&cnt_c, g_cnt_c);
    cudaGetSymbolAddress((void**)&cnt_w, g_cnt_w);
    cudaGetSymbolAddress((void**)&cnt_r, g_cnt_r);

    // ---- degree counts (layer invariant) ----
    cudaMemsetAsync(cnt_c, 0, NP * sizeof(float));
    cudaMemsetAsync(cnt_w, 0, NP * sizeof(float));
    cudaMemsetAsync(cnt_r, 0, NA * sizeof(float));
    count_kernel<<<(EC + 255) / 256, 256>>>(cd, cnt_c, EC);
    count_kernel<<<(EW + 255) / 256, 256>>>(wd, cnt_w, EW);
    count_kernel<<<(EW + 255) / 256, 256>>>(rd, cnt_r, EW);
    inv_kernel<<<(NP + 255) / 256, 256>>>(cnt_c, NP);
    inv_kernel<<<(NP + 255) / 256, 256>>>(cnt_w, NP);
    inv_kernel<<<(NA + 255) / 256, 256>>>(cnt_r, NA);

    const float* xpl = x_paper;
    const float* xal = x_author;
    for (int l = 0; l < 2; l++) {
        cudaMemsetAsync(acc_c, 0, (size_t)NP * H * sizeof(float));
        cudaMemsetAsync(acc_w, 0, (size_t)NP * H * sizeof(float));
        cudaMemsetAsync(acc_r, 0, (size_t)NA * H * sizeof(float));

        scatter_kernel<<<(EC + 7) / 8, 256>>>(xpl, cs, cd, acc_c, EC);
        scatter_kernel<<<(EW + 7) / 8, 256>>>(xal, ws, wd, acc_w, EW);
        scatter_kernel<<<(EW + 7) / 8, 256>>>(xpl, rs, rd, acc_r, EW);

        const float* const* Wb = W + l * 9;
        sage_gemm<<<(NP + 127) / 128, 256>>>(acc_c, cnt_c, xpl, Wb[0], Wb[2], Wb[1], Oc, NP);
        sage_gemm<<<(NP + 127) / 128, 256>>>(acc_w, cnt_w, xpl, Wb[3], Wb[5], Wb[4], Ow, NP);
        sage_gemm<<<(NA + 127) / 128, 256>>>(acc_r, cnt_r, xal, Wb[6], Wb[8], Wb[7], Or, NA);

        float* po = (l == 1) ? (float*)d_out : xp;
        float* ao = (l == 1) ? ((float*)d_out + (size_t)NP * H) : xa;
        finalize_paper<<<(NP * 32 + 255) / 256, 256>>>(Oc, Ow, po);
        finalize_author<<<(NA * 32 + 255) / 256, 256>>>(Or, ao);

        xpl = xp;
        xal = xa;
    }
    (void)n_in; (void)out_size; (void)x_author;
}

// round 3
// speedup vs baseline: 1.2602x; 1.2602x over previous
#include <cuda_runtime.h>
#include <cstdint>

#define NP 100000
#define NA 50000
#define H  128

// ---------------- device scratch ----------------
__device__ float g_acc_c[(size_t)NP * H];
__device__ float g_acc_w[(size_t)NP * H];
__device__ float g_acc_r[(size_t)NA * H];
__device__ float g_Oc[(size_t)NP * H];
__device__ float g_Ow[(size_t)NP * H];
__device__ float g_Or[(size_t)NA * H];
__device__ float g_xp[(size_t)NP * H];
__device__ float g_xa[(size_t)NA * H];
__device__ float g_cnt_c[NP];
__device__ float g_cnt_w[NP];
__device__ float g_cnt_r[NA];
__device__ float g_Whi[6][256 * 128];   // [k][n] tf32(hi) per (layer, edgetype)
__device__ float g_Wlo[6][256 * 128];   // [k][n] tf32(W - hi)

// ---------------- helpers ----------------
__device__ __forceinline__ uint32_t f2tf_u(float f) {
    uint32_t r;
    asm("cvt.rna.tf32.f32 %0, %1;" : "=r"(r) : "f"(f));
    return r;
}
__device__ __forceinline__ float f2tf_f(float f) { return __uint_as_float(f2tf_u(f)); }

// ---------------- small kernels ----------------
__global__ void count_kernel(const int* __restrict__ dst, float* __restrict__ cnt, int nE) {
    int e = blockIdx.x * blockDim.x + threadIdx.x;
    if (e < nE) atomicAdd(&cnt[dst[e]], 1.0f);
}
__global__ void inv_kernel(float* __restrict__ c, int n) {
    int i = blockIdx.x * blockDim.x + threadIdx.x;
    if (i < n) c[i] = 1.0f / fmaxf(c[i], 1.0f);
}
__global__ void scatter_kernel(const float* __restrict__ x, const int* __restrict__ src,
                               const int* __restrict__ dst, float* __restrict__ acc, int nE) {
    int gw   = (blockIdx.x * blockDim.x + threadIdx.x) >> 5;
    int lane = threadIdx.x & 31;
    if (gw >= nE) return;
    int s = __ldg(&src[gw]);
    int d = __ldg(&dst[gw]);
    float4 v = *(const float4*)(x + (size_t)s * H + lane * 4);
    float* p = acc + (size_t)d * H + lane * 4;
    unsigned long long gp = (unsigned long long)__cvta_generic_to_global(p);
    asm volatile("red.global.add.v4.f32 [%0], {%1, %2, %3, %4};"
                 :: "l"(gp), "f"(v.x), "f"(v.y), "f"(v.z), "f"(v.w) : "memory");
}
// Whi/Wlo[k][n]: k<128 -> Wl[k][n], else Wr[k-128][n]; hi = rna_tf32(w), lo = rna_tf32(w-hi)
__global__ void prep_split(const float* __restrict__ Wl, const float* __restrict__ Wr,
                           float* __restrict__ hi, float* __restrict__ lo) {
    int i = blockIdx.x * blockDim.x + threadIdx.x;   // 32768
    if (i < 256 * 128) {
        int k = i >> 7, nn = i & 127;
        float w = (k < 128) ? Wl[k * 128 + nn] : Wr[(k - 128) * 128 + nn];
        float h = f2tf_f(w);
        hi[i] = h;
        lo[i] = f2tf_f(w - h);
    }
}

// ---------------- tf32 mma.sync GEMM ----------------
// O[n x 128] = [acc*invc | xdst] (n x 256) @ (Whi + Wlo) (256 x 128) + bias
// CTA: 128x128 tile, 256 threads, 8 warps in 4(m) x 2(n); warp tile 32x64.
// K loop: 8 chunks of 32; per chunk do both hi and lo B mats.
#define AS_STRIDE 36
#define BS_STRIDE 132
#define SM_BIAS_OFF 0
#define SM_A_OFF    512
#define SM_BH_OFF   (SM_A_OFF + 128 * AS_STRIDE * 4)             // 512 + 18432
#define SM_BL_OFF   (SM_BH_OFF + 32 * BS_STRIDE * 4)             // + 16896
#define SM_GEMM_TOTAL (SM_BL_OFF + 32 * BS_STRIDE * 4)           // 52736

__global__ void __launch_bounds__(256, 2) sage_gemm_tc(
    const float* __restrict__ acc, const float* __restrict__ invc,
    const float* __restrict__ xdst,
    const float* __restrict__ Whi, const float* __restrict__ Wlo,
    const float* __restrict__ bias, float* __restrict__ O, int n)
{
    extern __shared__ char smem[];
    float* bs = (float*)(smem + SM_BIAS_OFF);
    float* As = (float*)(smem + SM_A_OFF);
    float* Bh = (float*)(smem + SM_BH_OFF);
    float* Bl = (float*)(smem + SM_BL_OFF);

    const int tid  = threadIdx.x;
    const int lane = tid & 31;
    const int wid  = tid >> 5;
    const int wm   = wid & 3;          // warp row (32 rows)
    const int wn   = wid >> 2;         // warp col (64 cols)
    const int row0 = blockIdx.x * 128;
    const int rq   = lane >> 2;        // 0..7
    const int cq   = lane & 3;         // 0..3

    if (tid < 128) bs[tid] = __ldg(&bias[tid]);
    __syncthreads();

    // C frags: [mt][nt][4]
    float c[2][8][4];
#pragma unroll
    for (int mt = 0; mt < 2; mt++)
#pragma unroll
        for (int nt = 0; nt < 8; nt++) {
            float b0 = bs[wn * 64 + nt * 8 + cq * 2];
            float b1 = bs[wn * 64 + nt * 8 + cq * 2 + 1];
            c[mt][nt][0] = b0; c[mt][nt][1] = b1;
            c[mt][nt][2] = b0; c[mt][nt][3] = b1;
        }

    for (int ch = 0; ch < 8; ch++) {
        const int kc = ch * 32;
        __syncthreads();   // protect previous chunk's smem from overwrite
        // ---- A tile: [128 m][32 k] fp32->tf32, pad 36 ----
#pragma unroll
        for (int l = 0; l < 4; l++) {
            int idx = tid + l * 256;            // 0..1023 float4 slots
            int r   = idx >> 3;
            int klv = (idx & 7) << 2;
            int rg  = row0 + r;
            float4 v = make_float4(0.f, 0.f, 0.f, 0.f);
            if (rg < n) {
                if (kc < 128) {
                    v = *(const float4*)(acc + (size_t)rg * H + kc + klv);
                    float ic = __ldg(&invc[rg]);
                    v.x *= ic; v.y *= ic; v.z *= ic; v.w *= ic;
                } else {
                    v = *(const float4*)(xdst + (size_t)rg * H + (kc - 128) + klv);
                }
            }
            float* p = As + r * AS_STRIDE + klv;
            p[0] = f2tf_f(v.x); p[1] = f2tf_f(v.y); p[2] = f2tf_f(v.z); p[3] = f2tf_f(v.w);
        }
        // ---- B tiles: Bh/Bl [32 k][128 n], pad 132; already tf32 bit patterns ----
#pragma unroll
        for (int l = 0; l < 8; l++) {
            int idx = tid + l * 256;            // 0..2047
            int mat = idx >> 10;
            int rem = idx & 1023;
            int k   = rem >> 5;
            int nv  = (rem & 31) << 2;
            const float* src = (mat ? Wlo : Whi) + (size_t)(kc + k) * 128 + nv;
            float4 v = *(const float4*)src;
            float* dstp = (mat ? Bl : Bh) + k * BS_STRIDE + nv;
            *(float4*)dstp = v;
        }
        __syncthreads();

        // ---- compute: 4 ksteps of 8 ----
#pragma unroll
        for (int ks = 0; ks < 4; ks++) {
            const int k0 = ks * 8;
            uint32_t au[2][4];
#pragma unroll
            for (int mt = 0; mt < 2; mt++) {
                const float* ap = As + (wm * 32 + mt * 16 + rq) * AS_STRIDE + k0 + cq;
                au[mt][0] = f2tf_u(ap[0]);
                au[mt][1] = f2tf_u(ap[8 * AS_STRIDE]);
                au[mt][2] = f2tf_u(ap[4]);
                au[mt][3] = f2tf_u(ap[8 * AS_STRIDE + 4]);
            }
#pragma unroll
            for (int mat = 0; mat < 2; mat++) {
                const float* B = mat ? Bl : Bh;
#pragma unroll
                for (int nt = 0; nt < 8; nt++) {
                    const float* bp = B + (k0 + cq) * BS_STRIDE + wn * 64 + nt * 8 + rq;
                    uint32_t b0 = __float_as_uint(bp[0]);
                    uint32_t b1 = __float_as_uint(bp[4 * BS_STRIDE]);
#pragma unroll
                    for (int mt = 0; mt < 2; mt++) {
                        asm volatile(
                            "mma.sync.aligned.m16n8k8.row.col.f32.tf32.tf32.f32 "
                            "{%0, %1, %2, %3}, {%4, %5, %6, %7}, {%8, %9}, {%0, %1, %2, %3};"
                            : "+f"(c[mt][nt][0]), "+f"(c[mt][nt][1]),
                              "+f"(c[mt][nt][2]), "+f"(c[mt][nt][3])
                            : "r"(au[mt][0]), "r"(au[mt][1]), "r"(au[mt][2]), "r"(au[mt][3]),
                              "r"(b0), "r"(b1));
                    }
                }
            }
        }
    }

    // ---- store ----
#pragma unroll
    for (int mt = 0; mt < 2; mt++) {
        int r = row0 + wm * 32 + mt * 16 + rq;
#pragma unroll
        for (int nt = 0; nt < 8; nt++) {
            int col = wn * 64 + nt * 8 + cq * 2;
            if (r < n)
                *(float2*)(O + (size_t)r * H + col) = make_float2(c[mt][nt][0], c[mt][nt][1]);
            if (r + 8 < n)
                *(float2*)(O + (size_t)(r + 8) * H + col) = make_float2(c[mt][nt][2], c[mt][nt][3]);
        }
    }
}

// ---------------- finalize ----------------
__global__ void finalize_paper(const float* __restrict__ Oc, const float* __restrict__ Ow,
                               float* __restrict__ out) {
    int gw   = (blockIdx.x * blockDim.x + threadIdx.x) >> 5;
    int lane = threadIdx.x & 31;
    if (gw >= NP) return;
    float4 cc = *(const float4*)(Oc + (size_t)gw * H + lane * 4);
    float4 w = *(const float4*)(Ow + (size_t)gw * H + lane * 4);
    float sc = cc.x*cc.x + cc.y*cc.y + cc.z*cc.z + cc.w*cc.w;
    float sw = w.x*w.x + w.y*w.y + w.z*w.z + w.w*w.w;
#pragma unroll
    for (int o = 16; o > 0; o >>= 1) {
        sc += __shfl_xor_sync(0xffffffffu, sc, o);
        sw += __shfl_xor_sync(0xffffffffu, sw, o);
    }
    float ic = 0.5f / fmaxf(sqrtf(sc), 1e-12f);
    float iw = 0.5f / fmaxf(sqrtf(sw), 1e-12f);
    float4 r;
    r.x = fmaxf(cc.x * ic + w.x * iw, 0.f);
    r.y = fmaxf(cc.y * ic + w.y * iw, 0.f);
    r.z = fmaxf(cc.z * ic + w.z * iw, 0.f);
    r.w = fmaxf(cc.w * ic + w.w * iw, 0.f);
    *(float4*)(out + (size_t)gw * H + lane * 4) = r;
}
__global__ void finalize_author(const float* __restrict__ Or, float* __restrict__ out) {
    int gw   = (blockIdx.x * blockDim.x + threadIdx.x) >> 5;
    int lane = threadIdx.x & 31;
    if (gw >= NA) return;
    float4 cc = *(const float4*)(Or + (size_t)gw * H + lane * 4);
    float sc = cc.x*cc.x + cc.y*cc.y + cc.z*cc.z + cc.w*cc.w;
#pragma unroll
    for (int o = 16; o > 0; o >>= 1) sc += __shfl_xor_sync(0xffffffffu, sc, o);
    float ic = 1.0f / fmaxf(sqrtf(sc), 1e-12f);
    float4 r;
    r.x = fmaxf(cc.x * ic, 0.f);
    r.y = fmaxf(cc.y * ic, 0.f);
    r.z = fmaxf(cc.z * ic, 0.f);
    r.w = fmaxf(cc.w * ic, 0.f);
    *(float4*)(out + (size_t)gw * H + lane * 4) = r;
}

// ---------------- host launcher ----------------
extern "C" void kernel_launch(void* const* d_in, const int* in_sizes, int n_in,
                              void* d_out, int out_size) {
    const float* x_paper  = (const float*)d_in[0];
    const float* x_author = (const float*)d_in[1];
    const int* cs = (const int*)d_in[2];
    const int* cd = (const int*)d_in[3];
    const int* ws = (const int*)d_in[4];
    const int* wd = (const int*)d_in[5];
    const int* rs = (const int*)d_in[6];
    const int* rd = (const int*)d_in[7];
    const int EC = in_sizes[2];
    const int EW = in_sizes[4];
    const float* W[18];
    for (int i = 0; i < 18; i++) W[i] = (const float*)d_in[8 + i];

    float *acc_c, *acc_w, *acc_r, *Oc, *Ow, *Or, *xp, *xa, *cnt_c, *cnt_w, *cnt_r, *WhiB, *WloB;
    cudaGetSymbolAddress((void**)&acc_c, g_acc_c);
    cudaGetSymbolAddress((void**)&acc_w, g_acc_w);
    cudaGetSymbolAddress((void**)&acc_r, g_acc_r);
    cudaGetSymbolAddress((void**)&Oc, g_Oc);
    cudaGetSymbolAddress((void**)&Ow, g_Ow);
    cudaGetSymbolAddress((void**)&Or, g_Or);
    cudaGetSymbolAddress((void**)&xp, g_xp);
    cudaGetSymbolAddress((void**)&xa, g_xa);
    cudaGetSymbolAddress((void**)&cnt_c, g_cnt_c);
    cudaGetSymbolAddress((void**)&cnt_w, g_cnt_w);
    cudaGetSymbolAddress((void**)&cnt_r, g_cnt_r);
    cudaGetSymbolAddress((void**)&WhiB, g_Whi);
    cudaGetSymbolAddress((void**)&WloB, g_Wlo);

    cudaFuncSetAttribute(sage_gemm_tc, cudaFuncAttributeMaxDynamicSharedMemorySize, SM_GEMM_TOTAL);

    // ---- degree counts (layer invariant) ----
    cudaMemsetAsync(cnt_c, 0, NP * sizeof(float));
    cudaMemsetAsync(cnt_w, 0, NP * sizeof(float));
    cudaMemsetAsync(cnt_r, 0, NA * sizeof(float));
    count_kernel<<<(EC + 255) / 256, 256>>>(cd, cnt_c, EC);
    count_kernel<<<(EW + 255) / 256, 256>>>(wd, cnt_w, EW);
    count_kernel<<<(EW + 255) / 256, 256>>>(rd, cnt_r, EW);
    inv_kernel<<<(NP + 255) / 256, 256>>>(cnt_c, NP);
    inv_kernel<<<(NP + 255) / 256, 256>>>(cnt_w, NP);
    inv_kernel<<<(NA + 255) / 256, 256>>>(cnt_r, NA);

    // ---- split weights once ----
    for (int l = 0; l < 2; l++)
        for (int t = 0; t < 3; t++) {
            const float* Wl = W[l * 9 + t * 3 + 0];
            const float* Wr = W[l * 9 + t * 3 + 2];
            prep_split<<<128, 256>>>(Wl, Wr,
                                     WhiB + (l * 3 + t) * 256 * 128,
                                     WloB + (l * 3 + t) * 256 * 128);
        }

    const float* xpl = x_paper;
    const float* xal = x_author;
    for (int l = 0; l < 2; l++) {
        cudaMemsetAsync(acc_c, 0, (size_t)NP * H * sizeof(float));
        cudaMemsetAsync(acc_w, 0, (size_t)NP * H * sizeof(float));
        cudaMemsetAsync(acc_r, 0, (size_t)NA * H * sizeof(float));

        scatter_kernel<<<(EC + 7) / 8, 256>>>(xpl, cs, cd, acc_c, EC);
        scatter_kernel<<<(EW + 7) / 8, 256>>>(xal, ws, wd, acc_w, EW);
        scatter_kernel<<<(EW + 7) / 8, 256>>>(xpl, rs, rd, acc_r, EW);

        const float* Whc = WhiB + (l * 3 + 0) * 256 * 128;
        const float* Wlc = WloB + (l * 3 + 0) * 256 * 128;
        const float* Whw = WhiB + (l * 3 + 1) * 256 * 128;
        const float* Wlw = WloB + (l * 3 + 1) * 256 * 128;
        const float* Whr = WhiB + (l * 3 + 2) * 256 * 128;
        const float* Wlr = WloB + (l * 3 + 2) * 256 * 128;

        sage_gemm_tc<<<(NP + 127) / 128, 256, SM_GEMM_TOTAL>>>(
            acc_c, cnt_c, xpl, Whc, Wlc, W[l * 9 + 1], Oc, NP);
        sage_gemm_tc<<<(NP + 127) / 128, 256, SM_GEMM_TOTAL>>>(
            acc_w, cnt_w, xpl, Whw, Wlw, W[l * 9 + 4], Ow, NP);
        sage_gemm_tc<<<(NA + 127) / 128, 256, SM_GEMM_TOTAL>>>(
            acc_r, cnt_r, xal, Whr, Wlr, W[l * 9 + 7], Or, NA);

        float* po = (l == 1) ? (float*)d_out : xp;
        float* ao = (l == 1) ? ((float*)d_out + (size_t)NP * H) : xa;
        finalize_paper<<<(NP * 32 + 255) / 256, 256>>>(Oc, Ow, po);
        finalize_author<<<(NA * 32 + 255) / 256, 256>>>(Or, ao);

        xpl = xp;
        xal = xa;
    }
    (void)n_in; (void)out_size; (void)x_author;
}

// round 4
// speedup vs baseline: 1.4744x; 1.1700x over previous
#include <cuda_runtime.h>
#include <cstdint>

#define NP 100000
#define NA 50000
#define H  128
#define EC_MAX 1000000
#define EW_MAX 320000

// ---------------- device scratch ----------------
__device__ float g_acc_c[(size_t)NP * H];
__device__ float g_acc_w[(size_t)NP * H];
__device__ float g_acc_r[(size_t)NA * H];
__device__ float g_Oc[(size_t)NP * H];
__device__ float g_Ow[(size_t)NP * H];
__device__ float g_Or[(size_t)NA * H];
__device__ float g_xp[(size_t)NP * H];
__device__ float g_xa[(size_t)NA * H];
__device__ float g_Whi[6][256 * 128];
__device__ float g_Wlo[6][256 * 128];
// CSR
__device__ int g_cnt_c[NP], g_cnt_w[NP], g_cnt_r[NA];
__device__ int g_rp_c[NP + 1], g_rp_w[NP + 1], g_rp_r[NA + 1];
__device__ int g_cur_c[NP], g_cur_w[NP], g_cur_r[NA];
__device__ int g_col_c[EC_MAX], g_col_w[EW_MAX], g_col_r[EW_MAX];

// ---------------- helpers ----------------
__device__ __forceinline__ uint32_t f2tf_u(float f) {
    uint32_t r;
    asm("cvt.rna.tf32.f32 %0, %1;" : "=r"(r) : "f"(f));
    return r;
}
__device__ __forceinline__ float f2tf_f(float f) { return __uint_as_float(f2tf_u(f)); }

// ---------------- CSR build ----------------
__global__ void counti_kernel(const int* __restrict__ dst, int* __restrict__ cnt, int nE) {
    int e = blockIdx.x * blockDim.x + threadIdx.x;
    if (e < nE) atomicAdd(&cnt[dst[e]], 1);
}

// single-block exclusive scan, 1024 threads, warp-shuffle based
__global__ void scan_kernel(const int* __restrict__ cnt, int* __restrict__ rp, int n) {
    __shared__ int wsum[32];
    __shared__ int s_off;
    const int tid = threadIdx.x, lane = tid & 31, wid = tid >> 5;
    if (tid == 0) s_off = 0;
    __syncthreads();
    for (int base = 0; base < n; base += 1024) {
        int i = base + tid;
        int v = (i < n) ? cnt[i] : 0;
        int incl = v;
#pragma unroll
        for (int o = 1; o < 32; o <<= 1) {
            int t = __shfl_up_sync(0xffffffffu, incl, o);
            if (lane >= o) incl += t;
        }
        if (lane == 31) wsum[wid] = incl;
        __syncthreads();
        if (wid == 0) {
            int w = wsum[lane];
            int wi = w;
#pragma unroll
            for (int o = 1; o < 32; o <<= 1) {
                int t = __shfl_up_sync(0xffffffffu, wi, o);
                if (lane >= o) wi += t;
            }
            wsum[lane] = wi - w;   // exclusive warp offset
        }
        __syncthreads();
        if (i < n) rp[i] = s_off + wsum[wid] + incl - v;
        __syncthreads();
        if (tid == 1023) s_off += wsum[31] + incl;
        __syncthreads();
    }
    if (tid == 0) rp[n] = s_off;
}

__global__ void fill_kernel(const int* __restrict__ src, const int* __restrict__ dst,
                            int* __restrict__ cur, int* __restrict__ col, int nE) {
    int e = blockIdx.x * blockDim.x + threadIdx.x;
    if (e < nE) {
        int d = dst[e];
        int p = atomicAdd(&cur[d], 1);
        col[p] = src[e];
    }
}

// ---------------- gather-mean aggregation: warp per dst node ----------------
__global__ void aggregate_kernel(const float* __restrict__ x, const int* __restrict__ rp,
                                 const int* __restrict__ col, float* __restrict__ acc, int n) {
    int gw   = (blockIdx.x * blockDim.x + threadIdx.x) >> 5;
    int lane = threadIdx.x & 31;
    if (gw >= n) return;
    const int beg = __ldg(&rp[gw]);
    const int end = __ldg(&rp[gw + 1]);
    float4 s = make_float4(0.f, 0.f, 0.f, 0.f);
    for (int b = beg; b < end; b += 32) {
        int nb = min(32, end - b);
        int my = (b + lane < end) ? __ldg(&col[b + lane]) : 0;
        for (int j = 0; j < nb; j++) {
            int sn = __shfl_sync(0xffffffffu, my, j);
            float4 v = *(const float4*)(x + (size_t)sn * H + lane * 4);
            s.x += v.x; s.y += v.y; s.z += v.z; s.w += v.w;
        }
    }
    float inv = 1.0f / fmaxf((float)(end - beg), 1.0f);
    s.x *= inv; s.y *= inv; s.z *= inv; s.w *= inv;
    *(float4*)(acc + (size_t)gw * H + lane * 4) = s;
}

// ---------------- weight split ----------------
__global__ void prep_split(const float* __restrict__ Wl, const float* __restrict__ Wr,
                           float* __restrict__ hi, float* __restrict__ lo) {
    int i = blockIdx.x * blockDim.x + threadIdx.x;
    if (i < 256 * 128) {
        int k = i >> 7, nn = i & 127;
        float w = (k < 128) ? Wl[k * 128 + nn] : Wr[(k - 128) * 128 + nn];
        float h = f2tf_f(w);
        hi[i] = h;
        lo[i] = f2tf_f(w - h);
    }
}

// ---------------- tf32 mma.sync GEMM ----------------
#define AS_STRIDE 36
#define BS_STRIDE 132
#define SM_BIAS_OFF 0
#define SM_A_OFF    512
#define SM_BH_OFF   (SM_A_OFF + 128 * AS_STRIDE * 4)
#define SM_BL_OFF   (SM_BH_OFF + 32 * BS_STRIDE * 4)
#define SM_GEMM_TOTAL (SM_BL_OFF + 32 * BS_STRIDE * 4)

__global__ void __launch_bounds__(256, 2) sage_gemm_tc(
    const float* __restrict__ acc, const float* __restrict__ xdst,
    const float* __restrict__ Whi, const float* __restrict__ Wlo,
    const float* __restrict__ bias, float* __restrict__ O, int n)
{
    extern __shared__ char smem[];
    float* bs = (float*)(smem + SM_BIAS_OFF);
    float* As = (float*)(smem + SM_A_OFF);
    float* Bh = (float*)(smem + SM_BH_OFF);
    float* Bl = (float*)(smem + SM_BL_OFF);

    const int tid  = threadIdx.x;
    const int lane = tid & 31;
    const int wid  = tid >> 5;
    const int wm   = wid & 3;
    const int wn   = wid >> 2;
    const int row0 = blockIdx.x * 128;
    const int rq   = lane >> 2;
    const int cq   = lane & 3;

    if (tid < 128) bs[tid] = __ldg(&bias[tid]);
    __syncthreads();

    float c[2][8][4];
#pragma unroll
    for (int mt = 0; mt < 2; mt++)
#pragma unroll
        for (int nt = 0; nt < 8; nt++) {
            float b0 = bs[wn * 64 + nt * 8 + cq * 2];
            float b1 = bs[wn * 64 + nt * 8 + cq * 2 + 1];
            c[mt][nt][0] = b0; c[mt][nt][1] = b1;
            c[mt][nt][2] = b0; c[mt][nt][3] = b1;
        }

    for (int ch = 0; ch < 8; ch++) {
        const int kc = ch * 32;
        __syncthreads();
        // A tile [128 m][32 k] -> tf32
#pragma unroll
        for (int l = 0; l < 4; l++) {
            int idx = tid + l * 256;
            int r   = idx >> 3;
            int klv = (idx & 7) << 2;
            int rg  = row0 + r;
            float4 v = make_float4(0.f, 0.f, 0.f, 0.f);
            if (rg < n) {
                const float* sp = (kc < 128)
                    ? acc  + (size_t)rg * H + kc + klv
                    : xdst + (size_t)rg * H + (kc - 128) + klv;
                v = *(const float4*)sp;
            }
            float* p = As + r * AS_STRIDE + klv;
            p[0] = f2tf_f(v.x); p[1] = f2tf_f(v.y); p[2] = f2tf_f(v.z); p[3] = f2tf_f(v.w);
        }
        // B tiles (already tf32)
#pragma unroll
        for (int l = 0; l < 8; l++) {
            int idx = tid + l * 256;
            int mat = idx >> 10;
            int rem = idx & 1023;
            int k   = rem >> 5;
            int nv  = (rem & 31) << 2;
            const float* src = (mat ? Wlo : Whi) + (size_t)(kc + k) * 128 + nv;
            float4 v = *(const float4*)src;
            float* dstp = (mat ? Bl : Bh) + k * BS_STRIDE + nv;
            *(float4*)dstp = v;
        }
        __syncthreads();

#pragma unroll
        for (int ks = 0; ks < 4; ks++) {
            const int k0 = ks * 8;
            uint32_t au[2][4];
#pragma unroll
            for (int mt = 0; mt < 2; mt++) {
                const float* ap = As + (wm * 32 + mt * 16 + rq) * AS_STRIDE + k0 + cq;
                au[mt][0] = __float_as_uint(ap[0]);
                au[mt][1] = __float_as_uint(ap[8 * AS_STRIDE]);
                au[mt][2] = __float_as_uint(ap[4]);
                au[mt][3] = __float_as_uint(ap[8 * AS_STRIDE + 4]);
            }
#pragma unroll
            for (int mat = 0; mat < 2; mat++) {
                const float* B = mat ? Bl : Bh;
#pragma unroll
                for (int nt = 0; nt < 8; nt++) {
                    const float* bp = B + (k0 + cq) * BS_STRIDE + wn * 64 + nt * 8 + rq;
                    uint32_t b0 = __float_as_uint(bp[0]);
                    uint32_t b1 = __float_as_uint(bp[4 * BS_STRIDE]);
#pragma unroll
                    for (int mt = 0; mt < 2; mt++) {
                        asm volatile(
                            "mma.sync.aligned.m16n8k8.row.col.f32.tf32.tf32.f32 "
                            "{%0, %1, %2, %3}, {%4, %5, %6, %7}, {%8, %9}, {%0, %1, %2, %3};"
                            : "+f"(c[mt][nt][0]), "+f"(c[mt][nt][1]),
                              "+f"(c[mt][nt][2]), "+f"(c[mt][nt][3])
                            : "r"(au[mt][0]), "r"(au[mt][1]), "r"(au[mt][2]), "r"(au[mt][3]),
                              "r"(b0), "r"(b1));
                    }
                }
            }
        }
    }

#pragma unroll
    for (int mt = 0; mt < 2; mt++) {
        int r = row0 + wm * 32 + mt * 16 + rq;
#pragma unroll
        for (int nt = 0; nt < 8; nt++) {
            int col = wn * 64 + nt * 8 + cq * 2;
            if (r < n)
                *(float2*)(O + (size_t)r * H + col) = make_float2(c[mt][nt][0], c[mt][nt][1]);
            if (r + 8 < n)
                *(float2*)(O + (size_t)(r + 8) * H + col) = make_float2(c[mt][nt][2], c[mt][nt][3]);
        }
    }
}

// ---------------- finalize ----------------
__global__ void finalize_paper(const float* __restrict__ Oc, const float* __restrict__ Ow,
                               float* __restrict__ out) {
    int gw   = (blockIdx.x * blockDim.x + threadIdx.x) >> 5;
    int lane = threadIdx.x & 31;
    if (gw >= NP) return;
    float4 cc = *(const float4*)(Oc + (size_t)gw * H + lane * 4);
    float4 w = *(const float4*)(Ow + (size_t)gw * H + lane * 4);
    float sc = cc.x*cc.x + cc.y*cc.y + cc.z*cc.z + cc.w*cc.w;
    float sw = w.x*w.x + w.y*w.y + w.z*w.z + w.w*w.w;
#pragma unroll
    for (int o = 16; o > 0; o >>= 1) {
        sc += __shfl_xor_sync(0xffffffffu, sc, o);
        sw += __shfl_xor_sync(0xffffffffu, sw, o);
    }
    float ic = 0.5f / fmaxf(sqrtf(sc), 1e-12f);
    float iw = 0.5f / fmaxf(sqrtf(sw), 1e-12f);
    float4 r;
    r.x = fmaxf(cc.x * ic + w.x * iw, 0.f);
    r.y = fmaxf(cc.y * ic + w.y * iw, 0.f);
    r.z = fmaxf(cc.z * ic + w.z * iw, 0.f);
    r.w = fmaxf(cc.w * ic + w.w * iw, 0.f);
    *(float4*)(out + (size_t)gw * H + lane * 4) = r;
}
__global__ void finalize_author(const float* __restrict__ Or, float* __restrict__ out) {
    int gw   = (blockIdx.x * blockDim.x + threadIdx.x) >> 5;
    int lane = threadIdx.x & 31;
    if (gw >= NA) return;
    float4 cc = *(const float4*)(Or + (size_t)gw * H + lane * 4);
    float sc = cc.x*cc.x + cc.y*cc.y + cc.z*cc.z + cc.w*cc.w;
#pragma unroll
    for (int o = 16; o > 0; o >>= 1) sc += __shfl_xor_sync(0xffffffffu, sc, o);
    float ic = 1.0f / fmaxf(sqrtf(sc), 1e-12f);
    float4 r;
    r.x = fmaxf(cc.x * ic, 0.f);
    r.y = fmaxf(cc.y * ic, 0.f);
    r.z = fmaxf(cc.z * ic, 0.f);
    r.w = fmaxf(cc.w * ic, 0.f);
    *(float4*)(out + (size_t)gw * H + lane * 4) = r;
}

// ---------------- host launcher ----------------
extern "C" void kernel_launch(void* const* d_in, const int* in_sizes, int n_in,
                              void* d_out, int out_size) {
    const float* x_paper  = (const float*)d_in[0];
    const float* x_author = (const float*)d_in[1];
    const int* cs = (const int*)d_in[2];
    const int* cd = (const int*)d_in[3];
    const int* ws = (const int*)d_in[4];
    const int* wd = (const int*)d_in[5];
    const int* rs = (const int*)d_in[6];
    const int* rd = (const int*)d_in[7];
    const int EC = in_sizes[2];
    const int EW = in_sizes[4];
    const float* W[18];
    for (int i = 0; i < 18; i++) W[i] = (const float*)d_in[8 + i];

    float *acc_c, *acc_w, *acc_r, *Oc, *Ow, *Or, *xp, *xa, *WhiB, *WloB;
    int *cnt_c, *cnt_w, *cnt_r, *rp_c, *rp_w, *rp_r, *cur_c, *cur_w, *cur_r, *col_c, *col_w, *col_r;
    cudaGetSymbolAddress((void**)&acc_c, g_acc_c);
    cudaGetSymbolAddress((void**)&acc_w, g_acc_w);
    cudaGetSymbolAddress((void**)&acc_r, g_acc_r);
    cudaGetSymbolAddress((void**)&Oc, g_Oc);
    cudaGetSymbolAddress((void**)&Ow, g_Ow);
    cudaGetSymbolAddress((void**)&Or, g_Or);
    cudaGetSymbolAddress((void**)&xp, g_xp);
    cudaGetSymbolAddress((void**)&xa, g_xa);
    cudaGetSymbolAddress((void**)&WhiB, g_Whi);
    cudaGetSymbolAddress((void**)&WloB, g_Wlo);
    cudaGetSymbolAddress((void**)&cnt_c, g_cnt_c);
    cudaGetSymbolAddress((void**)&cnt_w, g_cnt_w);
    cudaGetSymbolAddress((void**)&cnt_r, g_cnt_r);
    cudaGetSymbolAddress((void**)&rp_c, g_rp_c);
    cudaGetSymbolAddress((void**)&rp_w, g_rp_w);
    cudaGetSymbolAddress((void**)&rp_r, g_rp_r);
    cudaGetSymbolAddress((void**)&cur_c, g_cur_c);
    cudaGetSymbolAddress((void**)&cur_w, g_cur_w);
    cudaGetSymbolAddress((void**)&cur_r, g_cur_r);
    cudaGetSymbolAddress((void**)&col_c, g_col_c);
    cudaGetSymbolAddress((void**)&col_w, g_col_w);
    cudaGetSymbolAddress((void**)&col_r, g_col_r);

    cudaFuncSetAttribute(sage_gemm_tc, cudaFuncAttributeMaxDynamicSharedMemorySize, SM_GEMM_TOTAL);

    // ---- CSR build (per call; graph is layer-invariant) ----
    cudaMemsetAsync(cnt_c, 0, NP * sizeof(int));
    cudaMemsetAsync(cnt_w, 0, NP * sizeof(int));
    cudaMemsetAsync(cnt_r, 0, NA * sizeof(int));
    counti_kernel<<<(EC + 255) / 256, 256>>>(cd, cnt_c, EC);
    counti_kernel<<<(EW + 255) / 256, 256>>>(wd, cnt_w, EW);
    counti_kernel<<<(EW + 255) / 256, 256>>>(rd, cnt_r, EW);
    scan_kernel<<<1, 1024>>>(cnt_c, rp_c, NP);
    scan_kernel<<<1, 1024>>>(cnt_w, rp_w, NP);
    scan_kernel<<<1, 1024>>>(cnt_r, rp_r, NA);
    cudaMemcpyAsync(cur_c, rp_c, NP * sizeof(int), cudaMemcpyDeviceToDevice);
    cudaMemcpyAsync(cur_w, rp_w, NP * sizeof(int), cudaMemcpyDeviceToDevice);
    cudaMemcpyAsync(cur_r, rp_r, NA * sizeof(int), cudaMemcpyDeviceToDevice);
    fill_kernel<<<(EC + 255) / 256, 256>>>(cs, cd, cur_c, col_c, EC);
    fill_kernel<<<(EW + 255) / 256, 256>>>(ws, wd, cur_w, col_w, EW);
    fill_kernel<<<(EW + 255) / 256, 256>>>(rs, rd, cur_r, col_r, EW);

    // ---- split weights ----
    for (int l = 0; l < 2; l++)
        for (int t = 0; t < 3; t++) {
            const float* Wl = W[l * 9 + t * 3 + 0];
            const float* Wr = W[l * 9 + t * 3 + 2];
            prep_split<<<128, 256>>>(Wl, Wr,
                                     WhiB + (l * 3 + t) * 256 * 128,
                                     WloB + (l * 3 + t) * 256 * 128);
        }

    const float* xpl = x_paper;
    const float* xal = x_author;
    for (int l = 0; l < 2; l++) {
        aggregate_kernel<<<(NP * 32 + 255) / 256, 256>>>(xpl, rp_c, col_c, acc_c, NP);
        aggregate_kernel<<<(NP * 32 + 255) / 256, 256>>>(xal, rp_w, col_w, acc_w, NP);
        aggregate_kernel<<<(NA * 32 + 255) / 256, 256>>>(xpl, rp_r, col_r, acc_r, NA);

        const float* Whc = WhiB + (l * 3 + 0) * 256 * 128;
        const float* Wlc = WloB + (l * 3 + 0) * 256 * 128;
        const float* Whw = WhiB + (l * 3 + 1) * 256 * 128;
        const float* Wlw = WloB + (l * 3 + 1) * 256 * 128;
        const float* Whr = WhiB + (l * 3 + 2) * 256 * 128;
        const float* Wlr = WloB + (l * 3 + 2) * 256 * 128;

        sage_gemm_tc<<<(NP + 127) / 128, 256, SM_GEMM_TOTAL>>>(
            acc_c, xpl, Whc, Wlc, W[l * 9 + 1], Oc, NP);
        sage_gemm_tc<<<(NP + 127) / 128, 256, SM_GEMM_TOTAL>>>(
            acc_w, xpl, Whw, Wlw, W[l * 9 + 4], Ow, NP);
        sage_gemm_tc<<<(NA + 127) / 128, 256, SM_GEMM_TOTAL>>>(
            acc_r, xal, Whr, Wlr, W[l * 9 + 7], Or, NA);

        float* po = (l == 1) ? (float*)d_out : xp;
        float* ao = (l == 1) ? ((float*)d_out + (size_t)NP * H) : xa;
        finalize_paper<<<(NP * 32 + 255) / 256, 256>>>(Oc, Ow, po);
        finalize_author<<<(NA * 32 + 255) / 256, 256>>>(Or, ao);

        xpl = xp;
        xal = xa;
    }
    (void)n_in; (void)out_size; (void)x_author;
}

// round 5
// speedup vs baseline: 1.6841x; 1.1422x over previous
#include <cuda_runtime.h>
#include <cstdint>

#define NP 100000
#define NA 50000
#define H  128
#define EC_MAX 1000000
#define EW_MAX 320000

// ---------------- device scratch ----------------
__device__ float g_acc_c[(size_t)NP * H];
__device__ float g_acc_w[(size_t)NP * H];
__device__ float g_acc_r[(size_t)NA * H];
__device__ float g_Oc[(size_t)NP * H];
__device__ float g_Ow[(size_t)NP * H];
__device__ float g_Or[(size_t)NA * H];
__device__ float g_xp[(size_t)NP * H];
__device__ float g_xa[(size_t)NA * H];
__device__ float g_Whi[6][256 * 128];
__device__ float g_Wlo[6][256 * 128];
// CSR
__device__ int g_cnt_c[NP], g_cnt_w[NP], g_cnt_r[NA];
__device__ int g_rp_c[NP], g_rp_w[NP], g_rp_r[NA];
__device__ int g_cur_c[NP], g_cur_w[NP], g_cur_r[NA];
__device__ int g_col_c[EC_MAX], g_col_w[EW_MAX], g_col_r[EW_MAX];
__device__ int g_total[3];

// ---------------- helpers ----------------
__device__ __forceinline__ uint32_t f2tf_u(float f) {
    uint32_t r;
    asm("cvt.rna.tf32.f32 %0, %1;" : "=r"(r) : "f"(f));
    return r;
}
__device__ __forceinline__ float f2tf_f(float f) { return __uint_as_float(f2tf_u(f)); }

// ---------------- CSR build ----------------
__global__ void counti_kernel(const int* __restrict__ dst, int* __restrict__ cnt, int nE) {
    int e = blockIdx.x * blockDim.x + threadIdx.x;
    if (e < nE) atomicAdd(&cnt[dst[e]], 1);
}

// segment offset assignment: ordering-free replacement for an exclusive scan.
// warp-aggregates the per-thread counts so only one global atomic per warp.
__global__ void assign_kernel(const int* __restrict__ cnt, int* __restrict__ rp,
                              int* __restrict__ cur, int* __restrict__ total, int n) {
    int i = blockIdx.x * blockDim.x + threadIdx.x;
    int lane = threadIdx.x & 31;
    int v = (i < n) ? cnt[i] : 0;
    // warp inclusive scan of v
    int incl = v;
#pragma unroll
    for (int o = 1; o < 32; o <<= 1) {
        int t = __shfl_up_sync(0xffffffffu, incl, o);
        if (lane >= o) incl += t;
    }
    int wsum = __shfl_sync(0xffffffffu, incl, 31);
    int base = 0;
    if (lane == 31) base = atomicAdd(total, wsum);
    base = __shfl_sync(0xffffffffu, base, 31);
    int off = base + incl - v;
    if (i < n) { rp[i] = off; cur[i] = off; }
}

__global__ void fill_kernel(const int* __restrict__ src, const int* __restrict__ dst,
                            int* __restrict__ cur, int* __restrict__ col, int nE) {
    int e = blockIdx.x * blockDim.x + threadIdx.x;
    if (e < nE) {
        int d = dst[e];
        int p = atomicAdd(&cur[d], 1);
        col[p] = src[e];
    }
}

// ---------------- gather-mean aggregation: warp per dst node ----------------
__global__ void aggregate_kernel(const float* __restrict__ x, const int* __restrict__ rp,
                                 const int* __restrict__ cnt, const int* __restrict__ col,
                                 float* __restrict__ acc, int n) {
    int gw   = (blockIdx.x * blockDim.x + threadIdx.x) >> 5;
    int lane = threadIdx.x & 31;
    if (gw >= n) return;
    const int beg = __ldg(&rp[gw]);
    const int deg = __ldg(&cnt[gw]);
    const int end = beg + deg;
    float4 s = make_float4(0.f, 0.f, 0.f, 0.f);
    for (int b = beg; b < end; b += 32) {
        int nb = min(32, end - b);
        int my = (b + lane < end) ? __ldg(&col[b + lane]) : 0;
        for (int j = 0; j < nb; j++) {
            int sn = __shfl_sync(0xffffffffu, my, j);
            float4 v = *(const float4*)(x + (size_t)sn * H + lane * 4);
            s.x += v.x; s.y += v.y; s.z += v.z; s.w += v.w;
        }
    }
    float inv = 1.0f / fmaxf((float)deg, 1.0f);
    s.x *= inv; s.y *= inv; s.z *= inv; s.w *= inv;
    *(float4*)(acc + (size_t)gw * H + lane * 4) = s;
}

// ---------------- weight split ----------------
__global__ void prep_split(const float* __restrict__ Wl, const float* __restrict__ Wr,
                           float* __restrict__ hi, float* __restrict__ lo) {
    int i = blockIdx.x * blockDim.x + threadIdx.x;
    if (i < 256 * 128) {
        int k = i >> 7, nn = i & 127;
        float w = (k < 128) ? Wl[k * 128 + nn] : Wr[(k - 128) * 128 + nn];
        float h = f2tf_f(w);
        hi[i] = h;
        lo[i] = f2tf_f(w - h);
    }
}

// ---------------- tf32 mma.sync GEMM ----------------
#define AS_STRIDE 36
#define BS_STRIDE 132
#define SM_BIAS_OFF 0
#define SM_A_OFF    512
#define SM_BH_OFF   (SM_A_OFF + 128 * AS_STRIDE * 4)
#define SM_BL_OFF   (SM_BH_OFF + 32 * BS_STRIDE * 4)
#define SM_GEMM_TOTAL (SM_BL_OFF + 32 * BS_STRIDE * 4)

__global__ void __launch_bounds__(256, 2) sage_gemm_tc(
    const float* __restrict__ acc, const float* __restrict__ xdst,
    const float* __restrict__ Whi, const float* __restrict__ Wlo,
    const float* __restrict__ bias, float* __restrict__ O, int n)
{
    extern __shared__ char smem[];
    float* bs = (float*)(smem + SM_BIAS_OFF);
    float* As = (float*)(smem + SM_A_OFF);
    float* Bh = (float*)(smem + SM_BH_OFF);
    float* Bl = (float*)(smem + SM_BL_OFF);

    const int tid  = threadIdx.x;
    const int lane = tid & 31;
    const int wid  = tid >> 5;
    const int wm   = wid & 3;
    const int wn   = wid >> 2;
    const int row0 = blockIdx.x * 128;
    const int rq   = lane >> 2;
    const int cq   = lane & 3;

    if (tid < 128) bs[tid] = __ldg(&bias[tid]);
    __syncthreads();

    float c[2][8][4];
#pragma unroll
    for (int mt = 0; mt < 2; mt++)
#pragma unroll
        for (int nt = 0; nt < 8; nt++) {
            float b0 = bs[wn * 64 + nt * 8 + cq * 2];
            float b1 = bs[wn * 64 + nt * 8 + cq * 2 + 1];
            c[mt][nt][0] = b0; c[mt][nt][1] = b1;
            c[mt][nt][2] = b0; c[mt][nt][3] = b1;
        }

    for (int ch = 0; ch < 8; ch++) {
        const int kc = ch * 32;
        __syncthreads();
#pragma unroll
        for (int l = 0; l < 4; l++) {
            int idx = tid + l * 256;
            int r   = idx >> 3;
            int klv = (idx & 7) << 2;
            int rg  = row0 + r;
            float4 v = make_float4(0.f, 0.f, 0.f, 0.f);
            if (rg < n) {
                const float* sp = (kc < 128)
                    ? acc  + (size_t)rg * H + kc + klv
                    : xdst + (size_t)rg * H + (kc - 128) + klv;
                v = *(const float4*)sp;
            }
            float* p = As + r * AS_STRIDE + klv;
            p[0] = f2tf_f(v.x); p[1] = f2tf_f(v.y); p[2] = f2tf_f(v.z); p[3] = f2tf_f(v.w);
        }
#pragma unroll
        for (int l = 0; l < 8; l++) {
            int idx = tid + l * 256;
            int mat = idx >> 10;
            int rem = idx & 1023;
            int k   = rem >> 5;
            int nv  = (rem & 31) << 2;
            const float* src = (mat ? Wlo : Whi) + (size_t)(kc + k) * 128 + nv;
            float4 v = *(const float4*)src;
            float* dstp = (mat ? Bl : Bh) + k * BS_STRIDE + nv;
            *(float4*)dstp = v;
        }
        __syncthreads();

#pragma unroll
        for (int ks = 0; ks < 4; ks++) {
            const int k0 = ks * 8;
            uint32_t au[2][4];
#pragma unroll
            for (int mt = 0; mt < 2; mt++) {
                const float* ap = As + (wm * 32 + mt * 16 + rq) * AS_STRIDE + k0 + cq;
                au[mt][0] = __float_as_uint(ap[0]);
                au[mt][1] = __float_as_uint(ap[8 * AS_STRIDE]);
                au[mt][2] = __float_as_uint(ap[4]);
                au[mt][3] = __float_as_uint(ap[8 * AS_STRIDE + 4]);
            }
#pragma unroll
            for (int mat = 0; mat < 2; mat++) {
                const float* B = mat ? Bl : Bh;
#pragma unroll
                for (int nt = 0; nt < 8; nt++) {
                    const float* bp = B + (k0 + cq) * BS_STRIDE + wn * 64 + nt * 8 + rq;
                    uint32_t b0 = __float_as_uint(bp[0]);
                    uint32_t b1 = __float_as_uint(bp[4 * BS_STRIDE]);
#pragma unroll
                    for (int mt = 0; mt < 2; mt++) {
                        asm volatile(
                            "mma.sync.aligned.m16n8k8.row.col.f32.tf32.tf32.f32 "
                            "{%0, %1, %2, %3}, {%4, %5, %6, %7}, {%8, %9}, {%0, %1, %2, %3};"
                            : "+f"(c[mt][nt][0]), "+f"(c[mt][nt][1]),
                              "+f"(c[mt][nt][2]), "+f"(c[mt][nt][3])
                            : "r"(au[mt][0]), "r"(au[mt][1]), "r"(au[mt][2]), "r"(au[mt][3]),
                              "r"(b0), "r"(b1));
                    }
                }
            }
        }
    }

#pragma unroll
    for (int mt = 0; mt < 2; mt++) {
        int r = row0 + wm * 32 + mt * 16 + rq;
#pragma unroll
        for (int nt = 0; nt < 8; nt++) {
            int col = wn * 64 + nt * 8 + cq * 2;
            if (r < n)
                *(float2*)(O + (size_t)r * H + col) = make_float2(c[mt][nt][0], c[mt][nt][1]);
            if (r + 8 < n)
                *(float2*)(O + (size_t)(r + 8) * H + col) = make_float2(c[mt][nt][2], c[mt][nt][3]);
        }
    }
}

// ---------------- finalize ----------------
__global__ void finalize_paper(const float* __restrict__ Oc, const float* __restrict__ Ow,
                               float* __restrict__ out) {
    int gw   = (blockIdx.x * blockDim.x + threadIdx.x) >> 5;
    int lane = threadIdx.x & 31;
    if (gw >= NP) return;
    float4 cc = *(const float4*)(Oc + (size_t)gw * H + lane * 4);
    float4 w = *(const float4*)(Ow + (size_t)gw * H + lane * 4);
    float sc = cc.x*cc.x + cc.y*cc.y + cc.z*cc.z + cc.w*cc.w;
    float sw = w.x*w.x + w.y*w.y + w.z*w.z + w.w*w.w;
#pragma unroll
    for (int o = 16; o > 0; o >>= 1) {
        sc += __shfl_xor_sync(0xffffffffu, sc, o);
        sw += __shfl_xor_sync(0xffffffffu, sw, o);
    }
    float ic = 0.5f / fmaxf(sqrtf(sc), 1e-12f);
    float iw = 0.5f / fmaxf(sqrtf(sw), 1e-12f);
    float4 r;
    r.x = fmaxf(cc.x * ic + w.x * iw, 0.f);
    r.y = fmaxf(cc.y * ic + w.y * iw, 0.f);
    r.z = fmaxf(cc.z * ic + w.z * iw, 0.f);
    r.w = fmaxf(cc.w * ic + w.w * iw, 0.f);
    *(float4*)(out + (size_t)gw * H + lane * 4) = r;
}
__global__ void finalize_author(const float* __restrict__ Or, float* __restrict__ out) {
    int gw   = (blockIdx.x * blockDim.x + threadIdx.x) >> 5;
    int lane = threadIdx.x & 31;
    if (gw >= NA) return;
    float4 cc = *(const float4*)(Or + (size_t)gw * H + lane * 4);
    float sc = cc.x*cc.x + cc.y*cc.y + cc.z*cc.z + cc.w*cc.w;
#pragma unroll
    for (int o = 16; o > 0; o >>= 1) sc += __shfl_xor_sync(0xffffffffu, sc, o);
    float ic = 1.0f / fmaxf(sqrtf(sc), 1e-12f);
    float4 r;
    r.x = fmaxf(cc.x * ic, 0.f);
    r.y = fmaxf(cc.y * ic, 0.f);
    r.z = fmaxf(cc.z * ic, 0.f);
    r.w = fmaxf(cc.w * ic, 0.f);
    *(float4*)(out + (size_t)gw * H + lane * 4) = r;
}

// ---------------- host launcher ----------------
extern "C" void kernel_launch(void* const* d_in, const int* in_sizes, int n_in,
                              void* d_out, int out_size) {
    const float* x_paper  = (const float*)d_in[0];
    const float* x_author = (const float*)d_in[1];
    const int* cs = (const int*)d_in[2];
    const int* cd = (const int*)d_in[3];
    const int* ws = (const int*)d_in[4];
    const int* wd = (const int*)d_in[5];
    const int* rs = (const int*)d_in[6];
    const int* rd = (const int*)d_in[7];
    const int EC = in_sizes[2];
    const int EW = in_sizes[4];
    const float* W[18];
    for (int i = 0; i < 18; i++) W[i] = (const float*)d_in[8 + i];

    float *acc_c, *acc_w, *acc_r, *Oc, *Ow, *Or, *xp, *xa, *WhiB, *WloB;
    int *cnt_c, *cnt_w, *cnt_r, *rp_c, *rp_w, *rp_r, *cur_c, *cur_w, *cur_r;
    int *col_c, *col_w, *col_r, *total;
    cudaGetSymbolAddress((void**)&acc_c, g_acc_c);
    cudaGetSymbolAddress((void**)&acc_w, g_acc_w);
    cudaGetSymbolAddress((void**)&acc_r, g_acc_r);
    cudaGetSymbolAddress((void**)&Oc, g_Oc);
    cudaGetSymbolAddress((void**)&Ow, g_Ow);
    cudaGetSymbolAddress((void**)&Or, g_Or);
    cudaGetSymbolAddress((void**)&xp, g_xp);
    cudaGetSymbolAddress((void**)&xa, g_xa);
    cudaGetSymbolAddress((void**)&WhiB, g_Whi);
    cudaGetSymbolAddress((void**)&WloB, g_Wlo);
    cudaGetSymbolAddress((void**)&cnt_c, g_cnt_c);
    cudaGetSymbolAddress((void**)&cnt_w, g_cnt_w);
    cudaGetSymbolAddress((void**)&cnt_r, g_cnt_r);
    cudaGetSymbolAddress((void**)&rp_c, g_rp_c);
    cudaGetSymbolAddress((void**)&rp_w, g_rp_w);
    cudaGetSymbolAddress((void**)&rp_r, g_rp_r);
    cudaGetSymbolAddress((void**)&cur_c, g_cur_c);
    cudaGetSymbolAddress((void**)&cur_w, g_cur_w);
    cudaGetSymbolAddress((void**)&cur_r, g_cur_r);
    cudaGetSymbolAddress((void**)&col_c, g_col_c);
    cudaGetSymbolAddress((void**)&col_w, g_col_w);
    cudaGetSymbolAddress((void**)&col_r, g_col_r);
    cudaGetSymbolAddress((void**)&total, g_total);

    cudaFuncSetAttribute(sage_gemm_tc, cudaFuncAttributeMaxDynamicSharedMemorySize, SM_GEMM_TOTAL);

    // ---- CSR build ----
    cudaMemsetAsync(cnt_c, 0, NP * sizeof(int));
    cudaMemsetAsync(cnt_w, 0, NP * sizeof(int));
    cudaMemsetAsync(cnt_r, 0, NA * sizeof(int));
    cudaMemsetAsync(total, 0, 3 * sizeof(int));
    counti_kernel<<<(EC + 255) / 256, 256>>>(cd, cnt_c, EC);
    counti_kernel<<<(EW + 255) / 256, 256>>>(wd, cnt_w, EW);
    counti_kernel<<<(EW + 255) / 256, 256>>>(rd, cnt_r, EW);
    assign_kernel<<<(NP + 255) / 256, 256>>>(cnt_c, rp_c, cur_c, total + 0, NP);
    assign_kernel<<<(NP + 255) / 256, 256>>>(cnt_w, rp_w, cur_w, total + 1, NP);
    assign_kernel<<<(NA + 255) / 256, 256>>>(cnt_r, rp_r, cur_r, total + 2, NA);
    fill_kernel<<<(EC + 255) / 256, 256>>>(cs, cd, cur_c, col_c, EC);
    fill_kernel<<<(EW + 255) / 256, 256>>>(ws, wd, cur_w, col_w, EW);
    fill_kernel<<<(EW + 255) / 256, 256>>>(rs, rd, cur_r, col_r, EW);

    // ---- split weights ----
    for (int l = 0; l < 2; l++)
        for (int t = 0; t < 3; t++) {
            const float* Wl = W[l * 9 + t * 3 + 0];
            const float* Wr = W[l * 9 + t * 3 + 2];
            prep_split<<<128, 256>>>(Wl, Wr,
                                     WhiB + (l * 3 + t) * 256 * 128,
                                     WloB + (l * 3 + t) * 256 * 128);
        }

    const float* xpl = x_paper;
    const float* xal = x_author;
    for (int l = 0; l < 2; l++) {
        aggregate_kernel<<<(NP * 32 + 255) / 256, 256>>>(xpl, rp_c, cnt_c, col_c, acc_c, NP);
        aggregate_kernel<<<(NP * 32 + 255) / 256, 256>>>(xal, rp_w, cnt_w, col_w, acc_w, NP);
        aggregate_kernel<<<(NA * 32 + 255) / 256, 256>>>(xpl, rp_r, cnt_r, col_r, acc_r, NA);

        const float* Whc = WhiB + (l * 3 + 0) * 256 * 128;
        const float* Wlc = WloB + (l * 3 + 0) * 256 * 128;
        const float* Whw = WhiB + (l * 3 + 1) * 256 * 128;
        const float* Wlw = WloB + (l * 3 + 1) * 256 * 128;
        const float* Whr = WhiB + (l * 3 + 2) * 256 * 128;
        const float* Wlr = WloB + (l * 3 + 2) * 256 * 128;

        sage_gemm_tc<<<(NP + 127) / 128, 256, SM_GEMM_TOTAL>>>(
            acc_c, xpl, Whc, Wlc, W[l * 9 + 1], Oc, NP);
        sage_gemm_tc<<<(NP + 127) / 128, 256, SM_GEMM_TOTAL>>>(
            acc_w, xpl, Whw, Wlw, W[l * 9 + 4], Ow, NP);
        sage_gemm_tc<<<(NA + 127) / 128, 256, SM_GEMM_TOTAL>>>(
            acc_r, xal, Whr, Wlr, W[l * 9 + 7], Or, NA);

        float* po = (l == 1) ? (float*)d_out : xp;
        float* ao = (l == 1) ? ((float*)d_out + (size_t)NP * H) : xa;
        finalize_paper<<<(NP * 32 + 255) / 256, 256>>>(Oc, Ow, po);
        finalize_author<<<(NA * 32 + 255) / 256, 256>>>(Or, ao);

        xpl = xp;
        xal = xa;
    }
    (void)n_in; (void)out_size; (void)x_author;
}